// round 1
// baseline (speedup 1.0000x reference)
#include <cuda_runtime.h>
#include <cuda_bf16.h>

// Sparse transposed conv: gather-GEMM-scatter over rulebook.
// x:      [N_SRC, 32] f32
// weight: [K, 32, 16] f32
// src_idx:[K, M] i32
// dst_idx:[K, M] i32
// out:    [N_TGT, 16] f32 (atomic scatter-add)

#define CIN  32
#define COUT 16

__global__ __launch_bounds__(256)
void rulebook_gemm_scatter(const float* __restrict__ x,
                           const float* __restrict__ w,
                           const int*   __restrict__ src_idx,
                           const int*   __restrict__ dst_idx,
                           float*       __restrict__ out,
                           int M)
{
    __shared__ float wsm[CIN * COUT];   // weight[k], 2 KB

    const int k = blockIdx.y;
    // cooperative load of weight[k] into smem
    const float* wk = w + (size_t)k * CIN * COUT;
    for (int t = threadIdx.x; t < CIN * COUT; t += blockDim.x)
        wsm[t] = wk[t];
    __syncthreads();

    const int p = blockIdx.x * blockDim.x + threadIdx.x;
    if (p >= M) return;

    const long long base = (long long)k * M + p;
    const int s = __ldg(src_idx + base);
    const int d = __ldg(dst_idx + base);

    // gather one source row (128 B, aligned) via float4
    const float4* xr = reinterpret_cast<const float4*>(x + (size_t)s * CIN);
    float xv[CIN];
    #pragma unroll
    for (int q = 0; q < CIN / 4; q++) {
        float4 v = __ldg(xr + q);
        xv[q * 4 + 0] = v.x;
        xv[q * 4 + 1] = v.y;
        xv[q * 4 + 2] = v.z;
        xv[q * 4 + 3] = v.w;
    }

    float acc[COUT];
    #pragma unroll
    for (int j = 0; j < COUT; j++) acc[j] = 0.0f;

    #pragma unroll
    for (int c = 0; c < CIN; c++) {
        const float xc = xv[c];
        #pragma unroll
        for (int j = 0; j < COUT; j++)
            acc[j] = fmaf(xc, wsm[c * COUT + j], acc[j]);
    }

    float* o = out + (size_t)d * COUT;
    #pragma unroll
    for (int j = 0; j < COUT; j++)
        atomicAdd(o + j, acc[j]);
}

extern "C" void kernel_launch(void* const* d_in, const int* in_sizes, int n_in,
                              void* d_out, int out_size)
{
    const float* x       = (const float*)d_in[0];
    const float* weight  = (const float*)d_in[1];
    const int*   src_idx = (const int*)d_in[2];
    const int*   dst_idx = (const int*)d_in[3];
    float*       out     = (float*)d_out;

    const int K = in_sizes[1] / (CIN * COUT);       // 27
    const int M = in_sizes[2] / K;                  // 200000

    // zero the (poisoned) output — captured as a memset node
    cudaMemsetAsync(d_out, 0, (size_t)out_size * sizeof(float), 0);

    const int threads = 256;
    dim3 grid((M + threads - 1) / threads, K);
    rulebook_gemm_scatter<<<grid, threads>>>(x, weight, src_idx, dst_idx, out, M);
}

// round 2
// speedup vs baseline: 1.9868x; 1.9868x over previous
#include <cuda_runtime.h>
#include <cuda_bf16.h>

// Sparse transposed conv: gather-GEMM-scatter over rulebook.
// x:[N_SRC,32] f32, weight:[K,32,16] f32, src/dst:[K,M] i32, out:[N_TGT,16] f32.
// 4 pairs/thread (amortize weight LDS 4x), red.global.add.v4.f32 scatter.

#define CIN   32
#define COUT  16
#define PAIRS 4
#define TPB   128

__global__ __launch_bounds__(TPB)
void rulebook_gemm_scatter(const float* __restrict__ x,
                           const float* __restrict__ w,
                           const int*   __restrict__ src_idx,
                           const int*   __restrict__ dst_idx,
                           float*       __restrict__ out,
                           int M)
{
    __shared__ float wsm[CIN * COUT];   // weight[k], 2 KB

    const int k = blockIdx.y;
    const float* wk = w + (size_t)k * CIN * COUT;
    for (int t = threadIdx.x; t < CIN * COUT; t += TPB)
        wsm[t] = wk[t];
    __syncthreads();

    const int  base = blockIdx.x * (TPB * PAIRS) + threadIdx.x;
    const long long kb = (long long)k * M;

    int  s[PAIRS], d[PAIRS];
    bool valid[PAIRS];
    #pragma unroll
    for (int i = 0; i < PAIRS; i++) {
        const int p = base + i * TPB;           // coalesced index loads
        valid[i] = (p < M);
        s[i] = valid[i] ? __ldg(src_idx + kb + p) : 0;
        d[i] = valid[i] ? __ldg(dst_idx + kb + p) : 0;
    }

    float acc[PAIRS][COUT];
    #pragma unroll
    for (int i = 0; i < PAIRS; i++)
        #pragma unroll
        for (int j = 0; j < COUT; j++)
            acc[i][j] = 0.0f;

    // Chunked over CIN in groups of 4: per chunk, 4 divergent LDG.128 for x,
    // 16 broadcast LDS.128 for w (shared across the 4 pairs), 256 FFMA.
    #pragma unroll
    for (int cc = 0; cc < CIN; cc += 4) {
        float4 xv[PAIRS];
        #pragma unroll
        for (int i = 0; i < PAIRS; i++)
            xv[i] = __ldg(reinterpret_cast<const float4*>(x + (size_t)s[i] * CIN + cc));

        #pragma unroll
        for (int c4 = 0; c4 < 4; c4++) {
            const float4* wrow = reinterpret_cast<const float4*>(wsm + (cc + c4) * COUT);
            const float4 w0 = wrow[0], w1 = wrow[1], w2 = wrow[2], w3 = wrow[3];
            #pragma unroll
            for (int i = 0; i < PAIRS; i++) {
                const float xc = (c4 == 0) ? xv[i].x :
                                 (c4 == 1) ? xv[i].y :
                                 (c4 == 2) ? xv[i].z : xv[i].w;
                acc[i][ 0] = fmaf(xc, w0.x, acc[i][ 0]);
                acc[i][ 1] = fmaf(xc, w0.y, acc[i][ 1]);
                acc[i][ 2] = fmaf(xc, w0.z, acc[i][ 2]);
                acc[i][ 3] = fmaf(xc, w0.w, acc[i][ 3]);
                acc[i][ 4] = fmaf(xc, w1.x, acc[i][ 4]);
                acc[i][ 5] = fmaf(xc, w1.y, acc[i][ 5]);
                acc[i][ 6] = fmaf(xc, w1.z, acc[i][ 6]);
                acc[i][ 7] = fmaf(xc, w1.w, acc[i][ 7]);
                acc[i][ 8] = fmaf(xc, w2.x, acc[i][ 8]);
                acc[i][ 9] = fmaf(xc, w2.y, acc[i][ 9]);
                acc[i][10] = fmaf(xc, w2.z, acc[i][10]);
                acc[i][11] = fmaf(xc, w2.w, acc[i][11]);
                acc[i][12] = fmaf(xc, w3.x, acc[i][12]);
                acc[i][13] = fmaf(xc, w3.y, acc[i][13]);
                acc[i][14] = fmaf(xc, w3.z, acc[i][14]);
                acc[i][15] = fmaf(xc, w3.w, acc[i][15]);
            }
        }
    }

    // Scatter: 4 x red.global.add.v4.f32 per pair (out rows are 64B-aligned).
    #pragma unroll
    for (int i = 0; i < PAIRS; i++) {
        if (!valid[i]) continue;
        float* o = out + (size_t)d[i] * COUT;
        #pragma unroll
        for (int j = 0; j < COUT; j += 4) {
            asm volatile("red.global.add.v4.f32 [%0], {%1, %2, %3, %4};"
                         :: "l"(o + j),
                            "f"(acc[i][j + 0]), "f"(acc[i][j + 1]),
                            "f"(acc[i][j + 2]), "f"(acc[i][j + 3])
                         : "memory");
        }
    }
}

extern "C" void kernel_launch(void* const* d_in, const int* in_sizes, int n_in,
                              void* d_out, int out_size)
{
    const float* x       = (const float*)d_in[0];
    const float* weight  = (const float*)d_in[1];
    const int*   src_idx = (const int*)d_in[2];
    const int*   dst_idx = (const int*)d_in[3];
    float*       out     = (float*)d_out;

    const int K = in_sizes[1] / (CIN * COUT);       // 27
    const int M = in_sizes[2] / K;                  // 200000

    cudaMemsetAsync(d_out, 0, (size_t)out_size * sizeof(float), 0);

    const int pairs_per_block = TPB * PAIRS;        // 512
    dim3 grid((M + pairs_per_block - 1) / pairs_per_block, K);
    rulebook_gemm_scatter<<<grid, TPB>>>(x, weight, src_idx, dst_idx, out, M);
}

// round 3
// speedup vs baseline: 1.9975x; 1.0054x over previous
#include <cuda_runtime.h>

// Sparse transposed conv: gather-GEMM-scatter over rulebook.
// x:[N_SRC,32] f32, weight:[K,32,16] f32, src/dst:[K,M] i32, out:[N_TGT,16] f32.
// v3: smem-staged coalesced gather (xor-swizzled), f32x2 packed FMA,
//     red.global.add.v4.f32 scatter.

#define CIN   32
#define COUT  16
#define TPB   256
#define PPB   512              // pairs per block (2 per thread)
#define NITER ((PPB * 8) / TPB)  // 16 float4 staging iters

typedef unsigned long long ull;

#define FMA2(acc, a, b) \
    asm("fma.rn.f32x2 %0, %1, %2, %0;" : "+l"(acc) : "l"(a), "l"(b))

#define UNPACK2(lo, hi, v) \
    asm("mov.b64 {%0, %1}, %2;" : "=f"(lo), "=f"(hi) : "l"(v))

// dynamic smem layout:
//   [0,    2048)  wsm : 512 f32, interleaved: word = cp*32 + j*2 + (c&1)
//   [2048, 4096)  sidx: 512 i32
//   [4096, 69632) xsm : 512 rows * 8 float4 (xor-swizzled)
#define SMEM_BYTES (4096 + PPB * 8 * 16)

__global__ __launch_bounds__(TPB)
void rulebook_gemm_scatter(const float* __restrict__ x,
                           const float* __restrict__ w,
                           const int*   __restrict__ src_idx,
                           const int*   __restrict__ dst_idx,
                           float*       __restrict__ out,
                           int M)
{
    extern __shared__ char smem[];
    float*  wsm  = (float*)smem;
    int*    sidx = (int*)(smem + 2048);
    float4* xsm  = (float4*)(smem + 4096);

    const int k  = blockIdx.y;
    const int pb = blockIdx.x * PPB;
    const int npair = min(PPB, M - pb);
    const long long kb = (long long)k * M + pb;

    // weight[k] -> smem, f32x2-interleaved over channel pairs:
    // value (c, j) at word (c>>1)*32 + j*2 + (c&1)
    const float* wk = w + (size_t)k * (CIN * COUT);
    #pragma unroll
    for (int i = 0; i < (CIN * COUT) / TPB; i++) {
        int t = i * TPB + threadIdx.x;
        int c = t >> 4, j = t & 15;
        wsm[(c >> 1) * 32 + j * 2 + (c & 1)] = wk[t];
    }
    // src indices -> smem (needed by all staging lanes)
    #pragma unroll
    for (int i = 0; i < PPB / TPB; i++) {
        int t = i * TPB + threadIdx.x;
        sidx[t] = (t < npair) ? __ldg(src_idx + kb + t) : 0;
    }
    __syncthreads();

    // stage 512 gathered rows: 8 lanes per row -> coalesced 128B-line reads,
    // xor swizzle (slot j -> j ^ (r&7)) for conflict-free LDS.128 later.
    #pragma unroll
    for (int i = 0; i < NITER; i++) {
        int idx = i * TPB + threadIdx.x;
        int r = idx >> 3, j = idx & 7;
        float4 v = __ldg(reinterpret_cast<const float4*>(x) + (size_t)sidx[r] * 8 + j);
        xsm[r * 8 + (j ^ (r & 7))] = v;
    }
    __syncthreads();

    // compute: 2 pairs/thread (rows p0, p0+TPB); 16 f32x2 accumulators each,
    // halves hold even-c / odd-c partial sums.
    ull acc0[COUT], acc1[COUT];
    #pragma unroll
    for (int j = 0; j < COUT; j++) { acc0[j] = 0ull; acc1[j] = 0ull; }

    const int p0  = threadIdx.x;
    const int sw0 = p0 & 7;           // (p0+TPB)&7 == sw0 since TPB%8==0
    const longlong2* wsm2 = (const longlong2*)wsm;

    #pragma unroll
    for (int jj = 0; jj < 8; jj++) {
        longlong2 xa = *(const longlong2*)&xsm[p0 * 8 + (jj ^ sw0)];
        longlong2 xb = *(const longlong2*)&xsm[(p0 + TPB) * 8 + (jj ^ sw0)];
        #pragma unroll
        for (int h = 0; h < 2; h++) {
            const int cp = 2 * jj + h;                  // channel-pair index
            const ull x2a = (ull)(h ? xa.y : xa.x);     // (x[2cp], x[2cp+1])
            const ull x2b = (ull)(h ? xb.y : xb.x);
            #pragma unroll
            for (int q = 0; q < 8; q++) {               // broadcast LDS.128
                longlong2 wv = wsm2[cp * 8 + q];        // w2[j=2q], w2[j=2q+1]
                const ull w0 = (ull)wv.x, w1 = (ull)wv.y;
                FMA2(acc0[2 * q + 0], x2a, w0);
                FMA2(acc0[2 * q + 1], x2a, w1);
                FMA2(acc1[2 * q + 0], x2b, w0);
                FMA2(acc1[2 * q + 1], x2b, w1);
            }
        }
    }

    // reduce halves and scatter with red.global.add.v4.f32
    if (p0 < npair) {
        const int d0 = __ldg(dst_idx + kb + p0);
        float* o = out + (size_t)d0 * COUT;
        #pragma unroll
        for (int j = 0; j < COUT; j += 4) {
            float r0l, r0h, r1l, r1h, r2l, r2h, r3l, r3h;
            UNPACK2(r0l, r0h, acc0[j + 0]);
            UNPACK2(r1l, r1h, acc0[j + 1]);
            UNPACK2(r2l, r2h, acc0[j + 2]);
            UNPACK2(r3l, r3h, acc0[j + 3]);
            asm volatile("red.global.add.v4.f32 [%0], {%1, %2, %3, %4};"
                         :: "l"(o + j),
                            "f"(r0l + r0h), "f"(r1l + r1h),
                            "f"(r2l + r2h), "f"(r3l + r3h) : "memory");
        }
    }
    if (p0 + TPB < npair) {
        const int d1 = __ldg(dst_idx + kb + p0 + TPB);
        float* o = out + (size_t)d1 * COUT;
        #pragma unroll
        for (int j = 0; j < COUT; j += 4) {
            float r0l, r0h, r1l, r1h, r2l, r2h, r3l, r3h;
            UNPACK2(r0l, r0h, acc1[j + 0]);
            UNPACK2(r1l, r1h, acc1[j + 1]);
            UNPACK2(r2l, r2h, acc1[j + 2]);
            UNPACK2(r3l, r3h, acc1[j + 3]);
            asm volatile("red.global.add.v4.f32 [%0], {%1, %2, %3, %4};"
                         :: "l"(o + j),
                            "f"(r0l + r0h), "f"(r1l + r1h),
                            "f"(r2l + r2h), "f"(r3l + r3h) : "memory");
        }
    }
}

extern "C" void kernel_launch(void* const* d_in, const int* in_sizes, int n_in,
                              void* d_out, int out_size)
{
    const float* x       = (const float*)d_in[0];
    const float* weight  = (const float*)d_in[1];
    const int*   src_idx = (const int*)d_in[2];
    const int*   dst_idx = (const int*)d_in[3];
    float*       out     = (float*)d_out;

    const int K = in_sizes[1] / (CIN * COUT);   // 27
    const int M = in_sizes[2] / K;              // 200000

    cudaMemsetAsync(d_out, 0, (size_t)out_size * sizeof(float), 0);

    cudaFuncSetAttribute(rulebook_gemm_scatter,
                         cudaFuncAttributeMaxDynamicSharedMemorySize, SMEM_BYTES);

    dim3 grid((M + PPB - 1) / PPB, K);
    rulebook_gemm_scatter<<<grid, TPB, SMEM_BYTES>>>(x, weight, src_idx, dst_idx, out, M);
}

// round 5
// speedup vs baseline: 2.1124x; 1.0575x over previous
#include <cuda_runtime.h>
#include <cstdint>

// Sparse transposed conv: gather-GEMM-scatter over rulebook.
// x:[N_SRC,32] f32, weight:[K,32,16] f32, src/dst:[K,M] i32, out:[N_TGT,16] f32.
// v4b: cp.async staged gather (no RF round-trip), 3 blocks/SM, f32x2 FMA,
//      red.global.add.v4.f32 scatter, early dst prefetch.

#define CIN   32
#define COUT  16
#define TPB   256
#define PPB   512                 // pairs per block (2 per thread)
#define NITER ((PPB * 8) / TPB)   // 16 cp.async (16B) per thread

typedef unsigned long long ull;
typedef unsigned int       u32;

#define FMA2(acc, a, b) \
    asm("fma.rn.f32x2 %0, %1, %2, %0;" : "+l"(acc) : "l"(a), "l"(b))

#define UNPACK2(lo, hi, v) \
    asm("mov.b64 {%0, %1}, %2;" : "=f"(lo), "=f"(hi) : "l"(v))

// dynamic smem: [0,2048) wsm (f32x2-interleaved weight), [2048, 2048+64KB) xsm
#define XSM_OFF 2048
#define SMEM_BYTES (XSM_OFF + PPB * 8 * 16)

__global__ __launch_bounds__(TPB, 3)
void rulebook_gemm_scatter(const float* __restrict__ x,
                           const float* __restrict__ w,
                           const int*   __restrict__ src_idx,
                           const int*   __restrict__ dst_idx,
                           float*       __restrict__ out,
                           int M)
{
    extern __shared__ char smem[];
    float*  wsm = (float*)smem;
    float4* xsm = (float4*)(smem + XSM_OFF);

    const int k  = blockIdx.y;
    const int pb = blockIdx.x * PPB;
    const int npair = min(PPB, M - pb);
    const long long kb = (long long)k * M + pb;

    u32 xsm_base;
    asm("{ .reg .u64 t; cvta.to.shared.u64 t, %1; cvt.u32.u64 %0, t; }"
        : "=r"(xsm_base) : "l"(smem + XSM_OFF));

    // ---- stage 512 gathered rows with cp.async (8 lanes x 16B per row) ----
    #pragma unroll
    for (int i = 0; i < NITER; i++) {
        int idx = i * TPB + threadIdx.x;
        int r = idx >> 3, j = idx & 7;
        int rc = (r < npair) ? r : 0;
        int s = __ldg(src_idx + kb + rc);                 // 8-lane broadcast
        const float4* src = reinterpret_cast<const float4*>(x) + (size_t)s * 8 + j;
        u32 dst = xsm_base + (u32)(r * 8 + (j ^ (r & 7))) * 16;
        asm volatile("cp.async.cg.shared.global [%0], [%1], 16;"
                     :: "r"(dst), "l"(src));
    }
    asm volatile("cp.async.commit_group;");

    // ---- weight[k] -> smem, interleaved: word = cp*32 + j*2 + (c&1) ----
    const float* wk = w + (size_t)k * (CIN * COUT);
    #pragma unroll
    for (int i = 0; i < (CIN * COUT) / TPB; i++) {
        int t = i * TPB + threadIdx.x;
        int c = t >> 4, j = t & 15;
        wsm[(c >> 1) * 32 + j * 2 + (c & 1)] = __ldg(wk + t);
    }

    // prefetch scatter addresses while staging drains
    const int p0 = threadIdx.x;
    int d0 = 0, d1 = 0;
    if (p0 < npair)       d0 = __ldg(dst_idx + kb + p0);
    if (p0 + TPB < npair) d1 = __ldg(dst_idx + kb + p0 + TPB);

    asm volatile("cp.async.wait_group 0;");
    __syncthreads();

    // ---- compute: 2 pairs/thread, 16 f32x2 accs each (even-c/odd-c halves) ----
    ull acc0[COUT], acc1[COUT];
    #pragma unroll
    for (int j = 0; j < COUT; j++) { acc0[j] = 0ull; acc1[j] = 0ull; }

    const int sw0 = p0 & 7;                 // (p0+TPB)&7 == sw0 since TPB%8==0
    const longlong2* wsm2 = (const longlong2*)wsm;

    #pragma unroll
    for (int jj = 0; jj < 8; jj++) {
        longlong2 xa = *(const longlong2*)&xsm[p0 * 8 + (jj ^ sw0)];
        longlong2 xb = *(const longlong2*)&xsm[(p0 + TPB) * 8 + (jj ^ sw0)];
        #pragma unroll
        for (int h = 0; h < 2; h++) {
            const int cp = 2 * jj + h;                 // channel-pair index
            const ull x2a = (ull)(h ? xa.y : xa.x);    // (x[2cp], x[2cp+1])
            const ull x2b = (ull)(h ? xb.y : xb.x);
            #pragma unroll
            for (int q = 0; q < 8; q++) {              // broadcast LDS.128
                longlong2 wv = wsm2[cp * 8 + q];
                const ull w0 = (ull)wv.x, w1 = (ull)wv.y;
                FMA2(acc0[2 * q + 0], x2a, w0);
                FMA2(acc0[2 * q + 1], x2a, w1);
                FMA2(acc1[2 * q + 0], x2b, w0);
                FMA2(acc1[2 * q + 1], x2b, w1);
            }
        }
    }

    // ---- scatter: red.global.add.v4.f32, halves summed ----
    if (p0 < npair) {
        float* o = out + (size_t)d0 * COUT;
        #pragma unroll
        for (int j = 0; j < COUT; j += 4) {
            float r0l, r0h, r1l, r1h, r2l, r2h, r3l, r3h;
            UNPACK2(r0l, r0h, acc0[j + 0]);
            UNPACK2(r1l, r1h, acc0[j + 1]);
            UNPACK2(r2l, r2h, acc0[j + 2]);
            UNPACK2(r3l, r3h, acc0[j + 3]);
            asm volatile("red.global.add.v4.f32 [%0], {%1, %2, %3, %4};"
                         :: "l"(o + j),
                            "f"(r0l + r0h), "f"(r1l + r1h),
                            "f"(r2l + r2h), "f"(r3l + r3h) : "memory");
        }
    }
    if (p0 + TPB < npair) {
        float* o = out + (size_t)d1 * COUT;
        #pragma unroll
        for (int j = 0; j < COUT; j += 4) {
            float r0l, r0h, r1l, r1h, r2l, r2h, r3l, r3h;
            UNPACK2(r0l, r0h, acc1[j + 0]);
            UNPACK2(r1l, r1h, acc1[j + 1]);
            UNPACK2(r2l, r2h, acc1[j + 2]);
            UNPACK2(r3l, r3h, acc1[j + 3]);
            asm volatile("red.global.add.v4.f32 [%0], {%1, %2, %3, %4};"
                         :: "l"(o + j),
                            "f"(r0l + r0h), "f"(r1l + r1h),
                            "f"(r2l + r2h), "f"(r3l + r3h) : "memory");
        }
    }
}

extern "C" void kernel_launch(void* const* d_in, const int* in_sizes, int n_in,
                              void* d_out, int out_size)
{
    const float* x       = (const float*)d_in[0];
    const float* weight  = (const float*)d_in[1];
    const int*   src_idx = (const int*)d_in[2];
    const int*   dst_idx = (const int*)d_in[3];
    float*       out     = (float*)d_out;

    const int K = in_sizes[1] / (CIN * COUT);   // 27
    const int M = in_sizes[2] / K;              // 200000

    cudaMemsetAsync(d_out, 0, (size_t)out_size * sizeof(float), 0);

    cudaFuncSetAttribute(rulebook_gemm_scatter,
                         cudaFuncAttributeMaxDynamicSharedMemorySize, SMEM_BYTES);

    dim3 grid((M + PPB - 1) / PPB, K);
    rulebook_gemm_scatter<<<grid, TPB, SMEM_BYTES>>>(x, weight, src_idx, dst_idx, out, M);
}

// round 6
// speedup vs baseline: 2.5265x; 1.1960x over previous
#include <cuda_runtime.h>
#include <cstdint>

// Sparse transposed conv: gather-GEMM-scatter over rulebook.
// x:[N_SRC,32] f32, weight:[K,32,16] f32, src/dst:[K,M] i32, out:[N_TGT,16] f32.
// v5: cp.async staged gather, f32x2 FMA, smem-transposed scatter so each
//     red.global.add.v4.f32 warp-instr covers 8 pairs (8 lines, not 32).

#define CIN   32
#define COUT  16
#define TPB   256
#define PPB   512                 // pairs per block (2 per thread)
#define NITER ((PPB * 8) / TPB)   // 16 cp.async (16B) per thread

typedef unsigned long long ull;
typedef unsigned int       u32;

#define FMA2(acc, a, b) \
    asm("fma.rn.f32x2 %0, %1, %2, %0;" : "+l"(acc) : "l"(a), "l"(b))

#define UNPACK2(lo, hi, v) \
    asm("mov.b64 {%0, %1}, %2;" : "=f"(lo), "=f"(hi) : "l"(v))

// dynamic smem:
//   [0,2048)     wsm  : weight, f32x2-interleaved (word = cp*32 + j*2 + (c&1))
//   [2048,4096)  dsm  : 512 dst indices
//   [4096,+64K)  xsm  : staging rows (128B ea, xor-swizzled) ; reused after
//                       compute as scatter buffer (80B stride per pair)
#define DSM_OFF 2048
#define XSM_OFF 4096
#define SMEM_BYTES (XSM_OFF + PPB * 8 * 16)

__global__ __launch_bounds__(TPB, 3)
void rulebook_gemm_scatter(const float* __restrict__ x,
                           const float* __restrict__ w,
                           const int*   __restrict__ src_idx,
                           const int*   __restrict__ dst_idx,
                           float*       __restrict__ out,
                           int M)
{
    extern __shared__ char smem[];
    float*  wsm = (float*)smem;
    int*    dsm = (int*)(smem + DSM_OFF);
    float4* xsm = (float4*)(smem + XSM_OFF);

    const int k  = blockIdx.y;
    const int pb = blockIdx.x * PPB;
    const int npair = min(PPB, M - pb);
    const long long kb = (long long)k * M + pb;

    u32 xsm_base;
    asm("{ .reg .u64 t; cvta.to.shared.u64 t, %1; cvt.u32.u64 %0, t; }"
        : "=r"(xsm_base) : "l"(smem + XSM_OFF));

    // ---- stage 512 gathered rows with cp.async (8 lanes x 16B per row) ----
    #pragma unroll
    for (int i = 0; i < NITER; i++) {
        int idx = i * TPB + threadIdx.x;
        int r = idx >> 3, j = idx & 7;
        int rc = (r < npair) ? r : 0;
        int s = __ldg(src_idx + kb + rc);                 // 8-lane broadcast
        const float4* src = reinterpret_cast<const float4*>(x) + (size_t)s * 8 + j;
        u32 dst = xsm_base + (u32)(r * 8 + (j ^ (r & 7))) * 16;
        asm volatile("cp.async.cg.shared.global [%0], [%1], 16;"
                     :: "r"(dst), "l"(src));
    }
    asm volatile("cp.async.commit_group;");

    // ---- weight[k] -> smem (interleaved), dst indices -> smem ----
    const float* wk = w + (size_t)k * (CIN * COUT);
    #pragma unroll
    for (int i = 0; i < (CIN * COUT) / TPB; i++) {
        int t = i * TPB + threadIdx.x;
        int c = t >> 4, j = t & 15;
        wsm[(c >> 1) * 32 + j * 2 + (c & 1)] = __ldg(wk + t);
    }
    const int p0 = threadIdx.x;
    if (p0 < npair)       dsm[p0]       = __ldg(dst_idx + kb + p0);
    if (p0 + TPB < npair) dsm[p0 + TPB] = __ldg(dst_idx + kb + p0 + TPB);

    asm volatile("cp.async.wait_group 0;");
    __syncthreads();

    // ---- compute: 2 pairs/thread, 16 f32x2 accs each (even-c/odd-c halves) ----
    ull acc0[COUT], acc1[COUT];
    #pragma unroll
    for (int j = 0; j < COUT; j++) { acc0[j] = 0ull; acc1[j] = 0ull; }

    const int sw0 = p0 & 7;                 // (p0+TPB)&7 == sw0 since TPB%8==0
    const longlong2* wsm2 = (const longlong2*)wsm;

    #pragma unroll
    for (int jj = 0; jj < 8; jj++) {
        longlong2 xa = *(const longlong2*)&xsm[p0 * 8 + (jj ^ sw0)];
        longlong2 xb = *(const longlong2*)&xsm[(p0 + TPB) * 8 + (jj ^ sw0)];
        #pragma unroll
        for (int h = 0; h < 2; h++) {
            const int cp = 2 * jj + h;                 // channel-pair index
            const ull x2a = (ull)(h ? xa.y : xa.x);    // (x[2cp], x[2cp+1])
            const ull x2b = (ull)(h ? xb.y : xb.x);
            #pragma unroll
            for (int q = 0; q < 8; q++) {              // broadcast LDS.128
                longlong2 wv = wsm2[cp * 8 + q];
                const ull w0 = (ull)wv.x, w1 = (ull)wv.y;
                FMA2(acc0[2 * q + 0], x2a, w0);
                FMA2(acc0[2 * q + 1], x2a, w1);
                FMA2(acc1[2 * q + 0], x2b, w0);
                FMA2(acc1[2 * q + 1], x2b, w1);
            }
        }
    }
    __syncthreads();   // all staging reads done; xsm now reusable

    // ---- transpose results into smem: pair p's 16 floats at byte 80*p ----
    // 80B stride => 16B-bank = (5p + chunk) mod 8: conflict-free STS/LDS.
    float* sbuf = (float*)(smem + XSM_OFF);
    #pragma unroll
    for (int c4 = 0; c4 < 4; c4++) {
        float l0, h0, l1, h1;
        UNPACK2(l0, h0, acc0[4 * c4 + 0]);
        UNPACK2(l1, h1, acc0[4 * c4 + 1]);
        float a0 = l0 + h0, a1 = l1 + h1;
        UNPACK2(l0, h0, acc0[4 * c4 + 2]);
        UNPACK2(l1, h1, acc0[4 * c4 + 3]);
        *(float4*)(sbuf + p0 * 20 + c4 * 4) = make_float4(a0, a1, l0 + h0, l1 + h1);

        UNPACK2(l0, h0, acc1[4 * c4 + 0]);
        UNPACK2(l1, h1, acc1[4 * c4 + 1]);
        a0 = l0 + h0; a1 = l1 + h1;
        UNPACK2(l0, h0, acc1[4 * c4 + 2]);
        UNPACK2(l1, h1, acc1[4 * c4 + 3]);
        *(float4*)(sbuf + (p0 + TPB) * 20 + c4 * 4) = make_float4(a0, a1, l0 + h0, l1 + h1);
    }
    __syncthreads();

    // ---- scatter: 4 lanes per pair -> each red.v4 warp-instr = 8 pairs/8 lines ----
    #pragma unroll
    for (int i = 0; i < (PPB * 4) / TPB; i++) {        // 8 iters
        int g = i * TPB + threadIdx.x;
        int pair = g >> 2, chunk = g & 3;
        if (pair < npair) {
            float4 v = *(const float4*)(sbuf + pair * 20 + chunk * 4);
            float* o = out + (size_t)dsm[pair] * COUT + chunk * 4;
            asm volatile("red.global.add.v4.f32 [%0], {%1, %2, %3, %4};"
                         :: "l"(o), "f"(v.x), "f"(v.y), "f"(v.z), "f"(v.w)
                         : "memory");
        }
    }
}

extern "C" void kernel_launch(void* const* d_in, const int* in_sizes, int n_in,
                              void* d_out, int out_size)
{
    const float* x       = (const float*)d_in[0];
    const float* weight  = (const float*)d_in[1];
    const int*   src_idx = (const int*)d_in[2];
    const int*   dst_idx = (const int*)d_in[3];
    float*       out     = (float*)d_out;

    const int K = in_sizes[1] / (CIN * COUT);   // 27
    const int M = in_sizes[2] / K;              // 200000

    cudaMemsetAsync(d_out, 0, (size_t)out_size * sizeof(float), 0);

    cudaFuncSetAttribute(rulebook_gemm_scatter,
                         cudaFuncAttributeMaxDynamicSharedMemorySize, SMEM_BYTES);

    dim3 grid((M + PPB - 1) / PPB, K);
    rulebook_gemm_scatter<<<grid, TPB, SMEM_BYTES>>>(x, weight, src_idx, dst_idx, out, M);
}

// round 7
// speedup vs baseline: 3.2932x; 1.3035x over previous
#include <cuda_runtime.h>
#include <cstdint>

// Sparse transposed conv: gather-GEMM-scatter over rulebook.
// x:[N_SRC,32] f32, weight:[K,32,16] f32, src/dst:[K,M] i32, out:[N_TGT,16] f32.
// v6: 4-lane-per-pair ownership. Lane l owns couts 4l..4l+3 of its group's
//     4 pairs -> w LDS amortized 4x, scatter direct from registers
//     (red.v4 warp-instr = 8 pairs / 8 lines), no transpose phase.
//     PPB=256, 34KB smem, 4 blocks/SM.

#define CIN   32
#define COUT  16
#define TPB   256
#define PPB   256                 // pairs per block (4 per 4-lane group)
#define NITER ((PPB * 8) / TPB)   // 8 cp.async (16B) per thread

typedef unsigned long long ull;
typedef unsigned int       u32;

#define FMA2(acc, a, b) \
    asm("fma.rn.f32x2 %0, %1, %2, %0;" : "+l"(acc) : "l"(a), "l"(b))

#define UNPACK2(lo, hi, v) \
    asm("mov.b64 {%0, %1}, %2;" : "=f"(lo), "=f"(hi) : "l"(v))

// dynamic smem: [0,2048) wsm (f32x2-interleaved), [2048,+32K) xsm staging
#define XSM_OFF 2048
#define SMEM_BYTES (XSM_OFF + PPB * 8 * 16)   // 34816

__global__ __launch_bounds__(TPB, 4)
void rulebook_gemm_scatter(const float* __restrict__ x,
                           const float* __restrict__ w,
                           const int*   __restrict__ src_idx,
                           const int*   __restrict__ dst_idx,
                           float*       __restrict__ out,
                           int M)
{
    extern __shared__ char smem[];
    float*  wsm = (float*)smem;
    float4* xsm = (float4*)(smem + XSM_OFF);

    const int k  = blockIdx.y;
    const int pb = blockIdx.x * PPB;
    const int npair = min(PPB, M - pb);
    const long long kb = (long long)k * M + pb;

    u32 xsm_base;
    asm("{ .reg .u64 t; cvta.to.shared.u64 t, %1; cvt.u32.u64 %0, t; }"
        : "=r"(xsm_base) : "l"(smem + XSM_OFF));

    // ---- stage 256 gathered rows via cp.async (8 lanes x 16B per row) ----
    // swizzle: slot j -> j ^ ((r>>2)&7) so a warp's 8 groups hit 8 banks later
    #pragma unroll
    for (int i = 0; i < NITER; i++) {
        int idx = i * TPB + threadIdx.x;
        int r = idx >> 3, j = idx & 7;
        int rc = (r < npair) ? r : 0;
        int s = __ldg(src_idx + kb + rc);
        const float4* src = reinterpret_cast<const float4*>(x) + (size_t)s * 8 + j;
        u32 dst = xsm_base + (u32)(r * 8 + (j ^ ((r >> 2) & 7))) * 16;
        asm volatile("cp.async.cg.shared.global [%0], [%1], 16;"
                     :: "r"(dst), "l"(src));
    }
    asm volatile("cp.async.commit_group;");

    // ---- weight[k] -> smem, interleaved: word = cp*32 + j*2 + (c&1) ----
    const float* wk = w + (size_t)k * (CIN * COUT);
    #pragma unroll
    for (int i = 0; i < (CIN * COUT) / TPB; i++) {
        int t = i * TPB + threadIdx.x;
        int c = t >> 4, j = t & 15;
        wsm[(c >> 1) * 32 + j * 2 + (c & 1)] = __ldg(wk + t);
    }

    // group/lane decomposition: group g owns pairs g*4..g*4+3,
    // lane l of the group owns couts 4l..4l+3.
    const int g = threadIdx.x >> 2;
    const int l = threadIdx.x & 3;

    // prefetch scatter indices while staging drains
    int dsts[4];
    #pragma unroll
    for (int ii = 0; ii < 4; ii++) {
        int r = g * 4 + ii;
        dsts[ii] = (r < npair) ? __ldg(dst_idx + kb + r) : -1;
    }

    asm volatile("cp.async.wait_group 0;");
    __syncthreads();

    // ---- compute: acc[ii][m] (f32x2: even-c/odd-c halves), m = cout-4l ----
    ull acc[4][4];
    #pragma unroll
    for (int ii = 0; ii < 4; ii++)
        #pragma unroll
        for (int m = 0; m < 4; m++) acc[ii][m] = 0ull;

    const longlong2* wsm2 = (const longlong2*)wsm;
    const int sw = g & 7;

    #pragma unroll
    for (int jj = 0; jj < 8; jj++) {
        // w for cp=2jj,2jj+1 and couts 4l..4l+3 (4-lane spread, 8-way bcast)
        const longlong2 wa0 = wsm2[(2 * jj) * 8 + 2 * l];
        const longlong2 wa1 = wsm2[(2 * jj) * 8 + 2 * l + 1];
        const longlong2 wb0 = wsm2[(2 * jj + 1) * 8 + 2 * l];
        const longlong2 wb1 = wsm2[(2 * jj + 1) * 8 + 2 * l + 1];
        #pragma unroll
        for (int ii = 0; ii < 4; ii++) {
            const int r = g * 4 + ii;
            longlong2 xv = *(const longlong2*)&xsm[r * 8 + (jj ^ sw)];
            const ull xlo = (ull)xv.x;      // channels 4jj, 4jj+1 (cp 2jj)
            const ull xhi = (ull)xv.y;      // channels 4jj+2, 4jj+3 (cp 2jj+1)
            FMA2(acc[ii][0], xlo, (ull)wa0.x);
            FMA2(acc[ii][1], xlo, (ull)wa0.y);
            FMA2(acc[ii][2], xlo, (ull)wa1.x);
            FMA2(acc[ii][3], xlo, (ull)wa1.y);
            FMA2(acc[ii][0], xhi, (ull)wb0.x);
            FMA2(acc[ii][1], xhi, (ull)wb0.y);
            FMA2(acc[ii][2], xhi, (ull)wb1.x);
            FMA2(acc[ii][3], xhi, (ull)wb1.y);
        }
    }

    // ---- scatter direct from regs: each warp red.v4 = 8 pairs / 8 lines ----
    #pragma unroll
    for (int ii = 0; ii < 4; ii++) {
        if (dsts[ii] < 0) continue;
        float l0, h0, l1, h1, l2, h2, l3, h3;
        UNPACK2(l0, h0, acc[ii][0]);
        UNPACK2(l1, h1, acc[ii][1]);
        UNPACK2(l2, h2, acc[ii][2]);
        UNPACK2(l3, h3, acc[ii][3]);
        float* o = out + (size_t)dsts[ii] * COUT + 4 * l;
        asm volatile("red.global.add.v4.f32 [%0], {%1, %2, %3, %4};"
                     :: "l"(o),
                        "f"(l0 + h0), "f"(l1 + h1),
                        "f"(l2 + h2), "f"(l3 + h3) : "memory");
    }
}

extern "C" void kernel_launch(void* const* d_in, const int* in_sizes, int n_in,
                              void* d_out, int out_size)
{
    const float* x       = (const float*)d_in[0];
    const float* weight  = (const float*)d_in[1];
    const int*   src_idx = (const int*)d_in[2];
    const int*   dst_idx = (const int*)d_in[3];
    float*       out     = (float*)d_out;

    const int K = in_sizes[1] / (CIN * COUT);   // 27
    const int M = in_sizes[2] / K;              // 200000

    cudaMemsetAsync(d_out, 0, (size_t)out_size * sizeof(float), 0);

    cudaFuncSetAttribute(rulebook_gemm_scatter,
                         cudaFuncAttributeMaxDynamicSharedMemorySize, SMEM_BYTES);

    dim3 grid((M + PPB - 1) / PPB, K);
    rulebook_gemm_scatter<<<grid, TPB, SMEM_BYTES>>>(x, weight, src_idx, dst_idx, out, M);
}